// round 11
// baseline (speedup 1.0000x reference)
#include <cuda_runtime.h>
#include <cstdint>

#define VOCAB 32000
#define BOS_ID 1
#define BSZ 8
#define SEQLEN 2048

#define ROW4 (VOCAB / 4)          // 8000 float4 per (b,s) row
#define BLOCKS_PER_B 8000         // fill blocks per batch row (window = 2048 float4)

__device__ int g_pred[BSZ];

// ---------------------------------------------------------------------------
// Kernel A (upstream): per-row histogram + argmax (ties -> lowest index),
// BOS fallback. 8 blocks; ALL trigger PDL completion at entry, so the fill
// grid launches immediately and runs concurrently. Writes g_pred only.
// ---------------------------------------------------------------------------
__global__ void __launch_bounds__(1024) hist_kernel(const int* __restrict__ ids) {
    cudaTriggerProgrammaticLaunchCompletion();

    extern __shared__ int counts[];
    __shared__ int warp_best[32];

    const int b = blockIdx.x;
    const int t = threadIdx.x;

    int4* c4 = (int4*)counts;               // VOCAB/4 = 8000 int4
    #pragma unroll
    for (int i = t; i < VOCAB / 4; i += 1024) c4[i] = make_int4(0, 0, 0, 0);
    __syncthreads();

    const int* row = ids + b * SEQLEN;
    #pragma unroll
    for (int i = t; i < SEQLEN; i += 1024) {
        int v = row[i];
        if (v > BOS_ID) atomicAdd(&counts[v], 1);  // valid <=> v!=0 && v!=1 <=> v>1
    }
    __syncthreads();

    // Packed key: (count << 15) | (0x7FFF - v).
    // Higher count wins; equal count -> lower v wins (argmax tie rule).
    // count <= 2048 (12 bits), v < 32000 (15 bits) -> packed < 2^27.
    int best = 0;
    #pragma unroll
    for (int i = t; i < VOCAB / 4; i += 1024) {
        int4 c = c4[i];
        int vb = 0x7FFF - 4 * i;
        best = max(best, (c.x << 15) | vb);
        best = max(best, (c.y << 15) | (vb - 1));
        best = max(best, (c.z << 15) | (vb - 2));
        best = max(best, (c.w << 15) | (vb - 3));
    }
    best = __reduce_max_sync(0xFFFFFFFFu, best);
    if ((t & 31) == 0) warp_best[t >> 5] = best;
    __syncthreads();

    if (t < 32) {
        int wb = __reduce_max_sync(0xFFFFFFFFu, warp_best[t]);
        if (t == 0) {
            int cnt = wb >> 15;
            g_pred[b] = (cnt > 0) ? (0x7FFF - (wb & 0x7FFF)) : BOS_ID;
        }
    }
    // Kernel completion publishes g_pred; downstream griddepsync sees it.
}

// ---------------------------------------------------------------------------
// Kernel B (PDL downstream): pure -6 stream FIRST (no dependency), then
// griddepsync (hist finishes under the first wave's store drain), then the
// owning thread re-stores the single pred-column float4 in this block's
// window. Same-thread same-address ordering -> no fences anywhere.
// ---------------------------------------------------------------------------
__global__ void __launch_bounds__(256) fill_kernel(float4* __restrict__ out) {
    const int f = blockIdx.x;                 // 64000 blocks, window = 2048 float4
    const int t = threadIdx.x;

    // ---- 1. Pure -6 stream: 8 coalesced STG.128, zero index math. ----------
    const float4 neg = make_float4(-6.0f, -6.0f, -6.0f, -6.0f);
    float4* p = out + (long long)f * 2048 + t;
    #pragma unroll
    for (int j = 0; j < 8; j++) p[j * 256] = neg;

    // ---- 2. Wait for hist (overlapped with our own store drain). -----------
    cudaGridDependencySynchronize();

    // ---- 3. Patch: does this window contain the pred column? ---------------
    const int b   = f / BLOCKS_PER_B;         // batch row
    const int off = (f % BLOCKS_PER_B) * 2048;// float4 offset within batch
    const int c0  = off % ROW4;               // starting column of first row

    const int pred = __ldcg(&g_pred[b]);
    const int pc4  = pred >> 2;

    // Window covers row-s0 cols [c0, min(8000, c0+2048)) and, on spill,
    // row-s1 cols [0, c0+2048-8000). At most ONE position matches pc4.
    int idx = -1;                             // window-local float4 index
    if (pc4 >= c0 && pc4 < c0 + 2048 && pc4 < ROW4) idx = pc4 - c0;
    const int spill = c0 + 2048 - ROW4;
    if (spill > 0 && pc4 < spill) idx = (ROW4 - c0) + pc4;

    if (idx >= 0 && (idx & 255) == t) {
        float4 v = neg;
        reinterpret_cast<float*>(&v)[pred & 3] = 6.0f;
        out[(long long)f * 2048 + idx] = v;   // same thread wrote -6 here: ordered
    }
}

// ---------------------------------------------------------------------------
extern "C" void kernel_launch(void* const* d_in, const int* in_sizes, int n_in,
                              void* d_out, int out_size) {
    (void)in_sizes; (void)n_in; (void)out_size;
    const int* ids = (const int*)d_in[0];

    const int smem_bytes = VOCAB * (int)sizeof(int);  // 128000 bytes
    cudaFuncSetAttribute(hist_kernel,
                         cudaFuncAttributeMaxDynamicSharedMemorySize, smem_bytes);

    // Upstream: 8 blocks, all trigger at entry -> fill launches immediately.
    hist_kernel<<<BSZ, 1024, smem_bytes>>>(ids);

    // Downstream: PDL launch; stores run concurrently with hist, griddepsync
    // gates only the single-float4 patch.
    cudaLaunchConfig_t cfg = {};
    cfg.gridDim = dim3(64000);
    cfg.blockDim = dim3(256);
    cfg.dynamicSmemBytes = 0;
    cfg.stream = 0;
    cudaLaunchAttribute attrs[1];
    attrs[0].id = cudaLaunchAttributeProgrammaticStreamSerialization;
    attrs[0].val.programmaticStreamSerializationAllowed = 1;
    cfg.attrs = attrs;
    cfg.numAttrs = 1;
    cudaLaunchKernelEx(&cfg, fill_kernel, (float4*)d_out);
}

// round 12
// speedup vs baseline: 1.0961x; 1.0961x over previous
#include <cuda_runtime.h>
#include <cstdint>

#define VOCAB 32000
#define BOS_ID 1
#define BSZ 8
#define SEQLEN 2048

// Per-row majority token, computed by hist_kernel, consumed by fill_kernel.
__device__ int g_pred[BSZ];

// ---------------------------------------------------------------------------
// Kernel 1: per-row majority. Key insight: only tokens PRESENT in the row can
// win the argmax (present => count>=1 > 0; all-invalid => BOS fallback), so
// after accumulation each thread re-reads counts[] only at its own 2 token
// positions (2 LDS) instead of scanning all 32000 entries (32 LDS).
// One block per batch row; dynamic smem = VOCAB ints (128000 B, opt-in).
// ---------------------------------------------------------------------------
__global__ void __launch_bounds__(1024) hist_kernel(const int* __restrict__ ids) {
    extern __shared__ int counts[];
    __shared__ int warp_best[32];

    const int b = blockIdx.x;
    const int t = threadIdx.x;

    // Zero histogram: 8000 int4 / 1024 threads = 8 STS.128 each.
    int4* c4 = (int4*)counts;
    #pragma unroll
    for (int i = t; i < VOCAB / 4; i += 1024) c4[i] = make_int4(0, 0, 0, 0);
    __syncthreads();

    // Each thread owns 2 tokens of the row.
    const int* row = ids + b * SEQLEN;
    const int v0 = row[t];
    const int v1 = row[t + 1024];
    const bool ok0 = (v0 > BOS_ID);           // valid <=> v!=0 && v!=1 <=> v>1
    const bool ok1 = (v1 > BOS_ID);
    if (ok0) atomicAdd(&counts[v0], 1);
    if (ok1) atomicAdd(&counts[v1], 1);
    __syncthreads();

    // Packed key: (count << 15) | (0x7FFF - v).
    // Higher count wins; equal count -> lower v wins (argmax tie rule).
    // count <= 2048 (12 bits), v < 32000 (15 bits) -> packed < 2^27.
    int best = 0;
    if (ok0) best = (counts[v0] << 15) | (0x7FFF - v0);
    if (ok1) best = max(best, (counts[v1] << 15) | (0x7FFF - v1));

    best = __reduce_max_sync(0xFFFFFFFFu, best);
    if ((t & 31) == 0) warp_best[t >> 5] = best;
    __syncthreads();

    if (t < 32) {
        int wb = __reduce_max_sync(0xFFFFFFFFu, warp_best[t]);
        if (t == 0) {
            int cnt = wb >> 15;
            g_pred[b] = (cnt > 0) ? (0x7FFF - (wb & 0x7FFF)) : BOS_ID;
        }
    }
}

// ---------------------------------------------------------------------------
// Kernel 2: stream 2.1 GB of logits. One float4 (STG.128) per thread,
// pred-compare merged into the value BEFORE the store, nothing after it.
// grid = (64000, 8). Proven at 95.1% DRAM / 270.0us in R4.
// ---------------------------------------------------------------------------
__global__ void __launch_bounds__(256) fill_kernel(float4* __restrict__ out) {
    const int ROW4 = VOCAB / 4;                       // 8000 float4 per (b,s) row
    const long long per_b = (long long)SEQLEN * ROW4; // 16,384,000 float4 per batch

    const int b = blockIdx.y;
    const long long i_in_b = (long long)blockIdx.x * blockDim.x + threadIdx.x;
    const int r = (int)(i_in_b % ROW4);               // float4 index within vocab row

    const int pred = g_pred[b];

    float4 val = make_float4(-6.0f, -6.0f, -6.0f, -6.0f);
    const int vb = r * 4;
    if (pred >= vb && pred < vb + 4) {
        reinterpret_cast<float*>(&val)[pred - vb] = 6.0f;
    }

    out[(long long)b * per_b + i_in_b] = val;
}

// ---------------------------------------------------------------------------
extern "C" void kernel_launch(void* const* d_in, const int* in_sizes, int n_in,
                              void* d_out, int out_size) {
    (void)in_sizes; (void)n_in; (void)out_size;
    const int* ids = (const int*)d_in[0];
    float4* out = (float4*)d_out;

    const int smem_bytes = VOCAB * (int)sizeof(int);  // 128000 bytes
    cudaFuncSetAttribute(hist_kernel,
                         cudaFuncAttributeMaxDynamicSharedMemorySize, smem_bytes);

    hist_kernel<<<BSZ, 1024, smem_bytes>>>(ids);

    // SEQLEN * VOCAB/4 = 16,384,000 float4 per batch row; / 256 threads = 64000 blocks
    dim3 grid((SEQLEN * (VOCAB / 4)) / 256, BSZ);
    fill_kernel<<<grid, 256>>>(out);
}

// round 13
// speedup vs baseline: 1.0963x; 1.0001x over previous
#include <cuda_runtime.h>
#include <cstdint>

#define VOCAB 32000
#define BOS_ID 1
#define BSZ 8
#define SEQLEN 2048

#define ROW4 (VOCAB / 4)          // 8000 float4 per (b,s) row
#define BLOCKS_PER_B 8000         // fill blocks per batch row (window = 2048 float4)

// Per-row majority token, computed by hist_kernel, consumed by fill_kernel.
__device__ int g_pred[BSZ];

// ---------------------------------------------------------------------------
// Kernel 1: per-row majority. Only tokens PRESENT in the row can win the
// argmax (present => count>=1; all-invalid => BOS fallback), so each thread
// re-reads counts[] only at its own 2 token positions instead of scanning
// all 32000. One block per row; dynamic smem = VOCAB ints (128000 B).
// ---------------------------------------------------------------------------
__global__ void __launch_bounds__(1024) hist_kernel(const int* __restrict__ ids) {
    extern __shared__ int counts[];
    __shared__ int warp_best[32];

    const int b = blockIdx.x;
    const int t = threadIdx.x;

    int4* c4 = (int4*)counts;
    #pragma unroll
    for (int i = t; i < VOCAB / 4; i += 1024) c4[i] = make_int4(0, 0, 0, 0);
    __syncthreads();

    const int* row = ids + b * SEQLEN;
    const int v0 = row[t];
    const int v1 = row[t + 1024];
    const bool ok0 = (v0 > BOS_ID);           // valid <=> v!=0 && v!=1 <=> v>1
    const bool ok1 = (v1 > BOS_ID);
    if (ok0) atomicAdd(&counts[v0], 1);
    if (ok1) atomicAdd(&counts[v1], 1);
    __syncthreads();

    // Packed key: (count << 15) | (0x7FFF - v). Higher count wins; equal
    // count -> lower v (argmax tie rule). count<=2048 (12b), v<32000 (15b).
    int best = 0;
    if (ok0) best = (counts[v0] << 15) | (0x7FFF - v0);
    if (ok1) best = max(best, (counts[v1] << 15) | (0x7FFF - v1));

    best = __reduce_max_sync(0xFFFFFFFFu, best);
    if ((t & 31) == 0) warp_best[t >> 5] = best;
    __syncthreads();

    if (t < 32) {
        int wb = __reduce_max_sync(0xFFFFFFFFu, warp_best[t]);
        if (t == 0) {
            int cnt = wb >> 15;
            g_pred[b] = (cnt > 0) ? (0x7FFF - (wb & 0x7FFF)) : BOS_ID;
        }
    }
}

// ---------------------------------------------------------------------------
// Kernel 2: stream 2.1 GB. 64000 blocks x 256 threads x 8 STG.128.
// All expensive index math (div/mod) is block-constant, computed once;
// per-store cost = IADD + cond-sub + ISETP merged into the value BEFORE the
// store. Nothing executes after the stores.
// ---------------------------------------------------------------------------
__global__ void __launch_bounds__(256) fill_kernel(float4* __restrict__ out) {
    const int f = blockIdx.x;                 // window = 2048 float4 = 32KB
    const int t = threadIdx.x;

    const int b  = f / BLOCKS_PER_B;          // block-constant magic-div
    const int c0 = ((f % BLOCKS_PER_B) * 2048) % ROW4;  // start col of window

    const int pred = g_pred[b];
    const int pc4  = pred >> 2;
    const int lane = pred & 3;

    float4* p = out + (long long)f * 2048 + t;
    #pragma unroll
    for (int j = 0; j < 8; j++) {
        int s = c0 + j * 256 + t;             // column within vocab row
        if (s >= ROW4) s -= ROW4;             // at most one wrap per window
        float4 val = make_float4(-6.0f, -6.0f, -6.0f, -6.0f);
        if (s == pc4) reinterpret_cast<float*>(&val)[lane] = 6.0f;
        p[j * 256] = val;
    }
}

// ---------------------------------------------------------------------------
extern "C" void kernel_launch(void* const* d_in, const int* in_sizes, int n_in,
                              void* d_out, int out_size) {
    (void)in_sizes; (void)n_in; (void)out_size;
    const int* ids = (const int*)d_in[0];

    const int smem_bytes = VOCAB * (int)sizeof(int);  // 128000 bytes
    cudaFuncSetAttribute(hist_kernel,
                         cudaFuncAttributeMaxDynamicSharedMemorySize, smem_bytes);

    hist_kernel<<<BSZ, 1024, smem_bytes>>>(ids);
    fill_kernel<<<64000, 256>>>((float4*)d_out);
}